// round 17
// baseline (speedup 1.0000x reference)
#include <cuda_runtime.h>

#define NN 10000
#define NB 32
#define NE 320000
#define XS (NN*8)       // 80000 floats per batch
#define MAXDEG 128
#define XROW 12         // padded x row stride in floats (48B): (12g+t)%32 all-distinct

// ---------------- device scratch ----------------
__device__ __align__(128) int       g_counts[NN];
__device__ __align__(128) long long g_edge[NN * MAXDEG];   // (perm<<32)|col
__device__ __align__(128) float     g_xc[NN * NB * 8];     // xc[c][b*8+i], tf32-rounded

// ---------------- helpers ----------------
__device__ __forceinline__ float tf32r(float f) {
    unsigned u;
    asm("cvt.rna.tf32.f32 %0, %1;" : "=r"(u) : "f"(f));
    return __uint_as_float(u);
}
__device__ __forceinline__ void cp16(void* sdst, const void* gsrc) {
    unsigned sa = (unsigned)__cvta_generic_to_shared(sdst);
    asm volatile("cp.async.cg.shared.global [%0], [%1], 16;" :: "r"(sa), "l"(gsrc));
}
__device__ __forceinline__ void cp_commit() {
    asm volatile("cp.async.commit_group;" ::: "memory");
}
__device__ __forceinline__ void cp_wait1() {
    asm volatile("cp.async.wait_group 1;" ::: "memory");
}
__device__ __forceinline__ void mma_tf32(float* c, unsigned a0, unsigned a1,
                                         unsigned a2, unsigned a3,
                                         unsigned b0, unsigned b1) {
    asm("mma.sync.aligned.m16n8k8.row.col.f32.tf32.tf32.f32 "
        "{%0,%1,%2,%3}, {%4,%5,%6,%7}, {%8,%9}, {%0,%1,%2,%3};"
        : "+f"(c[0]), "+f"(c[1]), "+f"(c[2]), "+f"(c[3])
        : "r"(a0), "r"(a1), "r"(a2), "r"(a3), "r"(b0), "r"(b1));
}

// ---------------- 1) x transpose (tiled) + tf32 pre-round + zero counts ----------
__global__ __launch_bounds__(256) void transpose_kernel(const float* __restrict__ x) {
    __shared__ float s[8][260];
    int c0 = blockIdx.x * 32;
    int b0 = blockIdx.y * 8;
    int t  = threadIdx.x;
    int nc = min(32, NN - c0);
    int nf4 = nc * 2;

#pragma unroll
    for (int it = 0; it < 2; it++) {
        int id = it * 256 + t;
        int bl = id >> 6, f4 = id & 63;
        if (f4 < nf4) {
            float4 v = __ldg((const float4*)x + (long)(b0 + bl) * (XS / 4) + c0 * 2 + f4);
            *(float4*)&s[bl][f4 * 4] = v;
        }
    }
    __syncthreads();

#pragma unroll
    for (int it = 0; it < 2; it++) {
        int id = it * 256 + t;
        int cl = id >> 4, f4o = id & 15;
        if (cl < nc) {
            int bl = f4o >> 1;
            int i4 = (f4o & 1) * 4;
            float4 v = *(float4*)&s[bl][cl * 8 + i4];
            v.x = tf32r(v.x); v.y = tf32r(v.y); v.z = tf32r(v.z); v.w = tf32r(v.w);
            *((float4*)g_xc + (long)(c0 + cl) * 64 + (b0 + bl) * 2 + (f4o & 1)) = v;
        }
    }
    if (blockIdx.y == 0 && t < nc) g_counts[c0 + t] = 0;
}

// ---------------- 2) padded-bucket scatter ----------------
__global__ void scatter_kernel(const int* __restrict__ rows,
                               const int* __restrict__ cols) {
    int i = blockIdx.x * 256 + threadIdx.x;
    if (i < NE) {
        int r = __ldg(&rows[i]);
        int c = __ldg(&cols[i]);
        int p = atomicAdd(&g_counts[r], 1);
        if (p < MAXDEG)
            g_edge[(long)r * MAXDEG + p] = ((long long)i << 32) | (unsigned)c;
    }
}

// ---------------- 3) compute: WARP PER ROW, tf32 TENSOR CORES ----------------
// Per edge: out_tile[32x8] += X[32x8] @ V[8x8] as TWO mma.m16n8k8.tf32.
// x staged via cp.async into 48B-padded rows (A-frag LDS.32 conflict-free);
// v cvt.rna'd into smem (B-frag LDS.32 conflict-free).  Edge-pair pipeline (R11).
__global__ __launch_bounds__(32) void compute_kernel(
    const float* __restrict__ values,
    const float* __restrict__ bias,
    float* __restrict__ out)
{
    __shared__ __align__(16) float    sx[2][2][32 * XROW];  // [pairbuf][edge][b*12 + k]
    __shared__ __align__(16) unsigned sv[2][2][64];         // [pairbuf][edge][i*8 + j]

    int lane = threadIdx.x;
    int r    = blockIdx.x;
    int g    = lane >> 2;      // 0..7
    int t    = lane & 3;       // 0..3

    int n = min(g_counts[r], MAXDEG);
    const int4* eb4 = (const int4*)(g_edge + (long)r * MAXDEG); // {colA,permA,colB,permB}

    // cp chunk mapping: chunk k (0..63) -> b=k>>1, dst float off = (k>>1)*12+(k&1)*4
    int k1 = lane, k2 = lane + 32;
    int d1 = (k1 >> 1) * XROW + (k1 & 1) * 4;
    int d2 = (k2 >> 1) * XROW + (k2 & 1) * 4;

    float c[2][4];             // [half(batch 0-15 / 16-31)][c0..c3]
#pragma unroll
    for (int h = 0; h < 2; h++)
#pragma unroll
        for (int q = 0; q < 4; q++) c[h][q] = 0.0f;

    int P = (n + 1) >> 1;
    int4 e1;
    if (n > 0) {
        int4 e0 = __ldg(eb4);
        const float* xa = g_xc + (long)e0.x * 256;
        const float* xb = g_xc + (long)e0.z * 256;   // pad edge: stale-but-valid col
        cp16(&sx[0][0][d1], xa + k1 * 4);
        cp16(&sx[0][0][d2], xa + k2 * 4);
        cp16(&sx[0][1][d1], xb + k1 * 4);
        cp16(&sx[0][1][d2], xb + k2 * 4);
        cp_commit();
        float2 v0 = __ldcs((const float2*)(values + (long)e0.y * 64) + lane);
        float2 v1 = make_float2(0.0f, 0.0f);
        if (n > 1) v1 = __ldcs((const float2*)(values + (long)e0.w * 64) + lane);
        *(uint2*)&sv[0][0][2 * lane] =
            make_uint2(__float_as_uint(tf32r(v0.x)), __float_as_uint(tf32r(v0.y)));
        *(uint2*)&sv[0][1][2 * lane] =
            make_uint2(__float_as_uint(tf32r(v1.x)), __float_as_uint(tf32r(v1.y)));
        if (P > 1) e1 = __ldg(eb4 + 1);
    }

    for (int p = 0; p < P; p++) {
        bool more = (p + 1 < P);

        // ---- stage pair p+1: x via cp.async; v LDG now, cvt+STS after consume ----
        float2 van, vbn;
        if (more) {
            const float* xa = g_xc + (long)e1.x * 256;
            const float* xb = g_xc + (long)e1.z * 256;
            float* xd0 = &sx[(p + 1) & 1][0][0];
            float* xd1 = &sx[(p + 1) & 1][1][0];
            cp16(xd0 + d1, xa + k1 * 4);
            cp16(xd0 + d2, xa + k2 * 4);
            cp16(xd1 + d1, xb + k1 * 4);
            cp16(xd1 + d2, xb + k2 * 4);
            van = __ldcs((const float2*)(values + (long)e1.y * 64) + lane);
            vbn = make_float2(0.0f, 0.0f);
            if (2 * (p + 1) + 1 < n)
                vbn = __ldcs((const float2*)(values + (long)e1.w * 64) + lane);
        }
        cp_commit();                 // always: keeps group count invariant
        int4 e2;
        if (p + 2 < P) e2 = __ldg(eb4 + p + 2);

        cp_wait1();                  // pair p's x landed (pair p+1 may pend)
        __syncwarp();                // + pair p's v STS visible

        // ---- consume pair p: 2 edges x 2 MMAs ----
#pragma unroll
        for (int e = 0; e < 2; e++) {
            const float*    xs = &sx[p & 1][e][0];
            const unsigned* vs = &sv[p & 1][e][0];

            unsigned b0 = vs[t * 8 + g];            // V[k=t][j=g]
            unsigned b1 = vs[(t + 4) * 8 + g];      // V[k=t+4][j=g]

#pragma unroll
            for (int h = 0; h < 2; h++) {
                int rb = h * 16;
                unsigned a0 = __float_as_uint(xs[(rb + g)     * XROW + t]);
                unsigned a1 = __float_as_uint(xs[(rb + g + 8) * XROW + t]);
                unsigned a2 = __float_as_uint(xs[(rb + g)     * XROW + t + 4]);
                unsigned a3 = __float_as_uint(xs[(rb + g + 8) * XROW + t + 4]);
                mma_tf32(c[h], a0, a1, a2, a3, b0, b1);
            }
        }

        // ---- finish staging pair p+1's v; shift descriptor pipeline ----
        if (more) {
            *(uint2*)&sv[(p + 1) & 1][0][2 * lane] =
                make_uint2(__float_as_uint(tf32r(van.x)), __float_as_uint(tf32r(van.y)));
            *(uint2*)&sv[(p + 1) & 1][1][2 * lane] =
                make_uint2(__float_as_uint(tf32r(vbn.x)), __float_as_uint(tf32r(vbn.y)));
            e1 = e2;
        }
    }

    // ---- epilogue: C frag -> out (+bias).  c0,c1: row g, cols 2t,2t+1; c2,c3: row g+8.
    int ob = r * 8 + 2 * t;
    float2 bb = *(const float2*)(bias + ob);
#pragma unroll
    for (int h = 0; h < 2; h++) {
        int blo = h * 16 + g;
        float2 lo = make_float2(c[h][0] + bb.x, c[h][1] + bb.y);
        float2 hi = make_float2(c[h][2] + bb.x, c[h][3] + bb.y);
        *(float2*)(out + (long)blo       * XS + ob) = lo;
        *(float2*)(out + (long)(blo + 8) * XS + ob) = hi;
    }
}

// ---------------- launch ----------------
extern "C" void kernel_launch(void* const* d_in, const int* in_sizes, int n_in,
                              void* d_out, int out_size)
{
    const float* x      = (const float*)d_in[0];   // (32, 80000, 1)
    const float* values = (const float*)d_in[1];   // (320000, 8, 8)
    const float* bias   = (const float*)d_in[2];   // (80000,)
    const int*   idx    = (const int*)d_in[3];     // (2, 320000)
    float*       out    = (float*)d_out;

    const int* rows = idx;
    const int* cols = idx + NE;

    dim3 tgrid((NN + 31) / 32, NB / 8);
    transpose_kernel<<<tgrid, 256>>>(x);                     // launch 0
    scatter_kernel<<<(NE + 255) / 256, 256>>>(rows, cols);   // launch 1
    compute_kernel<<<NN, 32>>>(values, bias, out);           // launch 2 (idx 5 -> profiled)
}